// round 1
// baseline (speedup 1.0000x reference)
#include <cuda_runtime.h>

#define NQ 14
#define NL 4
#define DIM 16384            // 2^14
#define HALF_DIM 8192
#define NTHREADS 512
#define NWARPS (NTHREADS / 32)

// GF(2) linear-relabeling masks, computed host-side per launch, passed by value.
struct Masks {
    unsigned short d[NL][NQ];   // XOR pairing mask for RX(layer l, qubit q)
    unsigned short meas[NQ];    // parity mask: logical Z bit of qubit q after 4 CNOT layers
};

__global__ void __launch_bounds__(NTHREADS, 1)
qsim_kernel(const float* __restrict__ x, const float* __restrict__ params,
            float* __restrict__ out, Masks mk)
{
    extern __shared__ float2 st[];        // 16384 complex amplitudes = 128 KB
    __shared__ float xc[NQ], xs[NQ];      // embedding cos/sin
    __shared__ float gc[NL * NQ], gs[NL * NQ];  // gate cos/sin
    __shared__ float red[NWARPS][NQ];

    const int b   = blockIdx.x;
    const int tid = threadIdx.x;

    // ---- precompute trig in SMEM ----
    if (tid < NQ) {
        float v = 0.5f * x[b * NQ + tid];
        xc[tid] = cosf(v);
        xs[tid] = sinf(v);
    }
    if (tid >= 32 && tid < 32 + NL * NQ) {
        int g = tid - 32;
        float v = 0.5f * params[g];
        gc[g] = cosf(v);
        gs[g] = sinf(v);
    }
    __syncthreads();

    // ---- init RX-embedded product state ----
    // amp(p) = (-i)^popc(p) * prod_q (bit_q(p) ? sin(x_q/2) : cos(x_q/2))
    for (int p = tid; p < DIM; p += NTHREADS) {
        float mag = 1.0f;
        #pragma unroll
        for (int q = 0; q < NQ; ++q)
            mag *= ((p >> (NQ - 1 - q)) & 1) ? xs[q] : xc[q];
        int m = __popc(p) & 3;
        float2 a;
        a.x = (m == 0) ? mag : (m == 2 ? -mag : 0.0f);
        a.y = (m == 1) ? -mag : (m == 3 ? mag : 0.0f);
        st[p] = a;
    }
    __syncthreads();

    // ---- 4 layers x 14 RX gates; CNOT layers folded into the masks ----
    for (int l = 0; l < NL; ++l) {
        #pragma unroll 1
        for (int q = 0; q < NQ; ++q) {
            const unsigned d     = mk.d[l][q];
            const unsigned low   = d & (unsigned)(-(int)d);
            const unsigned lowm1 = low - 1u;
            const float c = gc[l * NQ + q];
            const float s = gs[l * NQ + q];
            for (int i = tid; i < HALF_DIM; i += NTHREADS) {
                // expand i to index p with the low bit of d cleared
                unsigned p  = ((i & ~lowm1) << 1) | (i & lowm1);
                unsigned pp = p ^ d;
                float2 a0 = st[p];
                float2 a1 = st[pp];
                float2 n0, n1;
                // RX: [[c, -i s],[-i s, c]] — exchange-symmetric, pair order irrelevant
                n0.x = c * a0.x + s * a1.y;
                n0.y = c * a0.y - s * a1.x;
                n1.x = c * a1.x + s * a0.y;
                n1.y = c * a1.y - s * a0.x;
                st[p]  = n0;
                st[pp] = n1;
            }
            __syncthreads();
        }
    }

    // ---- measurement: out[q] = sum_p |amp|^2 * (1 - 2*parity(p & meas[q])) ----
    float acc[NQ];
    #pragma unroll
    for (int q = 0; q < NQ; ++q) acc[q] = 0.0f;

    for (int p = tid; p < DIM; p += NTHREADS) {
        float2 a  = st[p];
        float  pr = a.x * a.x + a.y * a.y;
        #pragma unroll
        for (int q = 0; q < NQ; ++q)
            acc[q] += (__popc(p & (unsigned)mk.meas[q]) & 1) ? -pr : pr;
    }

    #pragma unroll
    for (int q = 0; q < NQ; ++q) {
        #pragma unroll
        for (int o = 16; o > 0; o >>= 1)
            acc[q] += __shfl_down_sync(0xffffffffu, acc[q], o);
    }
    const int warp = tid >> 5, lane = tid & 31;
    if (lane == 0) {
        #pragma unroll
        for (int q = 0; q < NQ; ++q) red[warp][q] = acc[q];
    }
    __syncthreads();
    if (tid < NQ) {
        float t = 0.0f;
        #pragma unroll
        for (int w = 0; w < NWARPS; ++w) t += red[w][tid];
        out[b * NQ + tid] = t;
    }
}

// ---- host-side GF(2) mask construction ----
// CNOT(q, q+1 mod 14) as index permutation: P(v) = v ^ (bit_ctrl(v) << tgt_pos)
static unsigned P_gate(unsigned v, int q) {
    int c = NQ - 1 - q;
    int t = NQ - 1 - ((q + 1) % NQ);
    return v ^ (((v >> c) & 1u) << t);
}
// Layer applies q = 0..13 in order; s_new[j] = s_old[Cinv(j)], Cinv = P0∘P1∘...∘P13 (P13 innermost)
static unsigned Capply(unsigned v)    { for (int q = 0;     q < NQ; ++q) v = P_gate(v, q); return v; }
static unsigned Cinvapply(unsigned v) { for (int q = NQ - 1; q >= 0; --q) v = P_gate(v, q); return v; }

extern "C" void kernel_launch(void* const* d_in, const int* in_sizes, int n_in,
                              void* d_out, int out_size)
{
    Masks mk;
    for (int l = 0; l < NL; ++l) {
        for (int q = 0; q < NQ; ++q) {
            unsigned m = 1u << (NQ - 1 - q);
            for (int k = 0; k < l; ++k) m = Cinvapply(m);   // d = C^{-l}(e_q)
            mk.d[l][q] = (unsigned short)m;
        }
    }
    // measurement masks: rows of C^4
    unsigned col[NQ];
    for (int j = 0; j < NQ; ++j) {
        unsigned v = 1u << j;
        for (int k = 0; k < NL; ++k) v = Capply(v);
        col[j] = v;
    }
    for (int q = 0; q < NQ; ++q) {
        unsigned mask = 0;
        int t = NQ - 1 - q;
        for (int j = 0; j < NQ; ++j) mask |= ((col[j] >> t) & 1u) << j;
        mk.meas[q] = (unsigned short)mask;
    }

    const int batch = in_sizes[0] / NQ;
    cudaFuncSetAttribute(qsim_kernel, cudaFuncAttributeMaxDynamicSharedMemorySize,
                         DIM * (int)sizeof(float2));
    qsim_kernel<<<batch, NTHREADS, DIM * sizeof(float2)>>>(
        (const float*)d_in[0], (const float*)d_in[1], (float*)d_out, mk);
}

// round 3
// speedup vs baseline: 2.0047x; 2.0047x over previous
#include <cuda_runtime.h>
#include <string.h>

#define NQ 14
#define NL 4
#define DIM 16384
#define NTHREADS 512
#define NWARPS (NTHREADS / 32)
#define NGATES (NL * NQ)          // 56
#define MAXG 20

typedef unsigned long long u64;

// Per-launch config, computed host-side, passed by value (kernel param space).
struct Cfg {
    int ngroups;
    unsigned short combo[MAXG][16];  // xor-combos of the group's 4 masks
    unsigned short lm[MAXG][4];      // expansion split masks ((1<<pivot)-1, ascending)
    signed char    gidx[MAXG][4];    // gate sequence index, or -1 = identity pad
    unsigned char  vq[NQ];           // WHT bucket per qubit (last group)
    unsigned short meas[NQ];         // Z-parity masks after all CNOT layers
};

// ---------- packed f32x2 helpers ----------
__device__ __forceinline__ u64 pkf(float lo, float hi) {
    u64 r; asm("mov.b64 %0,{%1,%2};" : "=l"(r) : "f"(lo), "f"(hi)); return r;
}
__device__ __forceinline__ void upk(u64 v, float& lo, float& hi) {
    asm("mov.b64 {%0,%1},%2;" : "=f"(lo), "=f"(hi) : "l"(v));
}
__device__ __forceinline__ u64 swp(u64 v) {
    float lo, hi; upk(v, lo, hi); return pkf(hi, lo);
}
__device__ __forceinline__ u64 mul2(u64 a, u64 b) {
    u64 d; asm("mul.rn.f32x2 %0,%1,%2;" : "=l"(d) : "l"(a), "l"(b)); return d;
}
__device__ __forceinline__ u64 fma2(u64 a, u64 b, u64 c) {
    u64 d; asm("fma.rn.f32x2 %0,%1,%2,%3;" : "=l"(d) : "l"(a), "l"(b), "l"(c)); return d;
}

__device__ __forceinline__ unsigned expand4(unsigned i, const unsigned short* lm) {
    unsigned p = i;
    #pragma unroll
    for (int k = 0; k < 4; ++k) {
        unsigned m = lm[k];
        p = ((p & ~m) << 1) | (p & m);
    }
    return p;
}

// Apply the 4 RX butterflies of group g to the 16-amp register tile.
// amp[t] packed (re,im); gate j pairs t <-> t^(1<<j).
// RX: n0 = c*a0 + (s*im1, -s*re1); exchange-symmetric so pair order is irrelevant.
#define APPLY_GROUP(amp, g)                                                  \
    do {                                                                     \
        _Pragma("unroll")                                                    \
        for (int j = 0; j < 4; ++j) {                                        \
            int gi = cfg.gidx[g][j];                                         \
            float c = (gi < 0) ? 1.0f : gc[gi];                              \
            float s = (gi < 0) ? 0.0f : gs[gi];                              \
            u64 cc = pkf(c, c), sn = pkf(s, -s);                             \
            _Pragma("unroll")                                                \
            for (int t = 0; t < 16; ++t) {                                   \
                if (t & (1 << j)) continue;                                  \
                int tb = t | (1 << j);                                       \
                u64 a0 = amp[t], a1 = amp[tb];                               \
                amp[t]  = fma2(cc, a0, mul2(sn, swp(a1)));                   \
                amp[tb] = fma2(cc, a1, mul2(sn, swp(a0)));                   \
            }                                                                \
        }                                                                    \
    } while (0)

__global__ void __launch_bounds__(NTHREADS, 1)
qsim_kernel(const float* __restrict__ x, const float* __restrict__ params,
            float* __restrict__ out, Cfg cfg)
{
    extern __shared__ u64 st[];              // 16384 packed amplitudes = 128 KB
    __shared__ float xc[NQ], xs[NQ];
    __shared__ float gc[NGATES], gs[NGATES];
    __shared__ float HT[16];                 // init: product table over qubits 0..3
    __shared__ unsigned short T0[32], T1[32];// sign-word tables for last-group base
    __shared__ float red[NWARPS][NQ];
    __shared__ float scr[NTHREADS * 17];     // WHT scatter scratch (pad 17: bank-free)

    const int b   = blockIdx.x;
    const int tid = threadIdx.x;
    const int ng  = cfg.ngroups;

    // ---- trig ----
    if (tid < NQ) {
        float v = 0.5f * x[b * NQ + tid];
        xc[tid] = cosf(v);
        xs[tid] = sinf(v);
    }
    if (tid >= 64 && tid < 64 + NGATES) {
        int g = tid - 64;
        float v = 0.5f * params[g];
        gc[g] = cosf(v);
        gs[g] = sinf(v);
    }
    __syncthreads();

    // ---- tables ----
    if (tid < 16) {
        float m = 1.0f;
        #pragma unroll
        for (int j = 0; j < 4; ++j) m *= ((tid >> j) & 1) ? xs[j] : xc[j];
        HT[tid] = m;
    }
    if (tid >= 32 && tid < 96) {
        int a = tid - 32;
        unsigned i10 = (a < 32) ? (unsigned)a : ((unsigned)(a - 32) << 5);
        unsigned p = expand4(i10, cfg.lm[ng - 1]);
        unsigned w = 0;
        #pragma unroll
        for (int q = 0; q < NQ; ++q)
            w |= (unsigned)(__popc(p & (unsigned)cfg.meas[q]) & 1) << q;
        if (a < 32) T0[a] = (unsigned short)w; else T1[a - 32] = (unsigned short)w;
    }
    __syncthreads();

    // ---- group 0: fused init (layer-0 masks are e0..e3 -> combos are bits 13..10) ----
    #pragma unroll 1
    for (int r = 0; r < 2; ++r) {
        const unsigned i = tid + (r << 9);
        float lowp = 1.0f;
        #pragma unroll
        for (int k = 0; k < 10; ++k)
            lowp *= ((i >> k) & 1) ? xs[13 - k] : xc[13 - k];
        u64 amp[16];
        #pragma unroll
        for (int t = 0; t < 16; ++t) {
            unsigned idx = i ^ (unsigned)cfg.combo[0][t];
            float mag = lowp * HT[t];
            int m = __popc(idx) & 3;
            float re = (m == 0) ? mag : ((m == 2) ? -mag : 0.0f);
            float im = (m == 1) ? -mag : ((m == 3) ? mag : 0.0f);
            amp[t] = pkf(re, im);
        }
        APPLY_GROUP(amp, 0);
        #pragma unroll
        for (int t = 0; t < 16; ++t)
            st[i ^ (unsigned)cfg.combo[0][t]] = amp[t];
    }
    __syncthreads();

    // ---- middle groups ----
    #pragma unroll 1
    for (int g = 1; g < ng - 1; ++g) {
        #pragma unroll 1
        for (int r = 0; r < 2; ++r) {
            const unsigned i = tid + (r << 9);
            unsigned p = expand4(i, cfg.lm[g]);
            u64 amp[16];
            #pragma unroll
            for (int t = 0; t < 16; ++t)
                amp[t] = st[p ^ (unsigned)cfg.combo[g][t]];
            APPLY_GROUP(amp, g);
            #pragma unroll
            for (int t = 0; t < 16; ++t)
                st[p ^ (unsigned)cfg.combo[g][t]] = amp[t];
        }
        __syncthreads();
    }

    // ---- last group: butterflies + fused measurement (16-pt WHT per tile) ----
    float acc[NQ];
    #pragma unroll
    for (int q = 0; q < NQ; ++q) acc[q] = 0.0f;

    {
        const int g = ng - 1;
        #pragma unroll 1
        for (int r = 0; r < 2; ++r) {
            const unsigned i = tid + (r << 9);
            unsigned p = expand4(i, cfg.lm[g]);
            u64 amp[16];
            #pragma unroll
            for (int t = 0; t < 16; ++t)
                amp[t] = st[p ^ (unsigned)cfg.combo[g][t]];
            APPLY_GROUP(amp, g);

            float pr[16];
            #pragma unroll
            for (int t = 0; t < 16; ++t) {
                float re, im; upk(amp[t], re, im);
                pr[t] = re * re + im * im;
            }
            // 16-point WHT: WHT[v] = sum_t pr[t]*(-1)^popc(v&t)
            #pragma unroll
            for (int j = 0; j < 4; ++j) {
                #pragma unroll
                for (int t = 0; t < 16; ++t) {
                    if (t & (1 << j)) continue;
                    int tb = t | (1 << j);
                    float a = pr[t], bb = pr[tb];
                    pr[t] = a + bb; pr[tb] = a - bb;
                }
            }
            #pragma unroll
            for (int t = 0; t < 16; ++t) scr[tid * 17 + t] = pr[t];
            unsigned wb = (unsigned)T0[i & 31] ^ (unsigned)T1[(i >> 5) & 31];
            #pragma unroll
            for (int q = 0; q < NQ; ++q) {
                float v = scr[tid * 17 + cfg.vq[q]];
                acc[q] += ((wb >> q) & 1) ? -v : v;
            }
        }
    }

    // ---- reduce across threads ----
    #pragma unroll
    for (int q = 0; q < NQ; ++q) {
        #pragma unroll
        for (int o = 16; o > 0; o >>= 1)
            acc[q] += __shfl_down_sync(0xffffffffu, acc[q], o);
    }
    const int warp = tid >> 5, lane = tid & 31;
    if (lane == 0) {
        #pragma unroll
        for (int q = 0; q < NQ; ++q) red[warp][q] = acc[q];
    }
    __syncthreads();
    if (tid < NQ) {
        float t = 0.0f;
        #pragma unroll
        for (int w = 0; w < NWARPS; ++w) t += red[w][tid];
        out[b * NQ + tid] = t;
    }
}

// ================= host side =================
// CNOT(q, q+1 mod 14) as GF(2) index map (qubit 0 = MSB = bit 13).
static unsigned P_gate(unsigned v, int q) {
    int c = NQ - 1 - q;
    int t = NQ - 1 - ((q + 1) % NQ);
    return v ^ (((v >> c) & 1u) << t);
}
static unsigned Capply(unsigned v)    { for (int q = 0;      q < NQ; ++q) v = P_gate(v, q); return v; }
static unsigned Cinvapply(unsigned v) { for (int q = NQ - 1; q >= 0; --q) v = P_gate(v, q); return v; }

// xor-basis insert keyed by highest bit; returns false if v in span.
static bool basis_add(unsigned* pos, unsigned v) {
    for (int b = NQ - 1; b >= 0; --b) {
        if (!((v >> b) & 1)) continue;
        if (!pos[b]) { pos[b] = v; return true; }
        v ^= pos[b];
    }
    return false;
}

extern "C" void kernel_launch(void* const* d_in, const int* in_sizes, int n_in,
                              void* d_out, int out_size)
{
    Cfg cfg;
    memset(&cfg, 0, sizeof(cfg));

    // gate mask sequence: layer l gate q acts on storage pairs p <-> p ^ C^{-l}(e_q)
    unsigned seq[NGATES];
    int si = 0;
    for (int l = 0; l < NL; ++l)
        for (int q = 0; q < NQ; ++q) {
            unsigned m = 1u << (NQ - 1 - q);
            for (int k = 0; k < l; ++k) m = Cinvapply(m);
            seq[si++] = m;
        }

    // greedy grouping into independent quads (identity padding on failure)
    unsigned gmask[MAXG][4];
    unsigned pos[NQ];
    int ng = 0, cnt = 0;
    memset(pos, 0, sizeof(pos));
    auto close_group = [&]() {
        while (cnt < 4) {  // pad with an independent single-bit identity gate
            for (int bb = 0; bb < NQ; ++bb) {
                if (basis_add(pos, 1u << bb)) {
                    gmask[ng][cnt] = 1u << bb;
                    cfg.gidx[ng][cnt] = -1;
                    ++cnt;
                    break;
                }
            }
        }
        // pivots ascending -> split masks
        int k = 0;
        for (int bb = 0; bb < NQ; ++bb)
            if (pos[bb]) cfg.lm[ng][k++] = (unsigned short)((1u << bb) - 1u);
        // combos
        for (int t = 0; t < 16; ++t) {
            unsigned cbo = 0;
            for (int j = 0; j < 4; ++j) if ((t >> j) & 1) cbo ^= gmask[ng][j];
            cfg.combo[ng][t] = (unsigned short)cbo;
        }
        ++ng;
        cnt = 0;
        memset(pos, 0, sizeof(pos));
    };
    for (int s = 0; s < NGATES; ++s) {
        if (cnt == 4 || !basis_add(pos, seq[s])) {
            close_group();
            basis_add(pos, seq[s]);
        }
        gmask[ng][cnt] = seq[s];
        cfg.gidx[ng][cnt] = (signed char)s;
        ++cnt;
    }
    close_group();
    cfg.ngroups = ng;

    // measurement parity masks (rows of C^NL), identical to validated R1 code
    unsigned col[NQ];
    for (int j = 0; j < NQ; ++j) {
        unsigned v = 1u << j;
        for (int k = 0; k < NL; ++k) v = Capply(v);
        col[j] = v;
    }
    for (int q = 0; q < NQ; ++q) {
        unsigned mask = 0;
        int t = NQ - 1 - q;
        for (int j = 0; j < NQ; ++j) mask |= ((col[j] >> t) & 1u) << j;
        cfg.meas[q] = (unsigned short)mask;
    }

    // WHT bucket per qubit from the LAST group's masks
    for (int q = 0; q < NQ; ++q) {
        unsigned v = 0;
        for (int j = 0; j < 4; ++j) {
            unsigned par = (unsigned)(__builtin_popcount(gmask[ng - 1][j] & cfg.meas[q]) & 1);
            v |= par << j;
        }
        cfg.vq[q] = (unsigned char)v;
    }

    const int batch = in_sizes[0] / NQ;
    cudaFuncSetAttribute(qsim_kernel, cudaFuncAttributeMaxDynamicSharedMemorySize,
                         DIM * (int)sizeof(u64));
    qsim_kernel<<<batch, NTHREADS, DIM * sizeof(u64)>>>(
        (const float*)d_in[0], (const float*)d_in[1], (float*)d_out, cfg);
}

// round 6
// speedup vs baseline: 3.5283x; 1.7600x over previous
#include <cuda_runtime.h>
#include <string.h>

#define NQ 14
#define NL 4
#define DIM 16384
#define NTHREADS 512
#define NWARPS 16
#define NGATES 56          // NL * NQ
#define MAXG 20
#define HIMASK 0x3FE0u     // bits 5..13

struct Cfg {
    int ngroups;
    unsigned short combo[MAXG][16];  // storage-frame xor combos of group's masks
    unsigned short lm[MAXG][4];      // split masks (1<<pivot)-1, pivots ascending
    signed char    gidx[MAXG][4];    // gate seq index, -1 = identity pad
    unsigned short gseq[NGATES];     // storage-frame gate masks (for D accumulation)
    unsigned short meas[NQ];         // storage-frame Z parity masks
    unsigned char  vq[NQ];           // WHT bucket per qubit (last group)
    unsigned short c0log[16];        // sigma^-1(combo[0][t]) for fused init
    unsigned short illo[128];        // sigma^-1 of low 7 bits
    unsigned short ilhi[128];        // sigma^-1 of high 7 bits
};

__device__ __forceinline__ unsigned expand4(unsigned i, const unsigned short* lm) {
    unsigned p = i;
    #pragma unroll
    for (int k = 0; k < 4; ++k) {
        unsigned m = lm[k];
        p = ((p & ~m) << 1) | (p & m);
    }
    return p;
}

// 4 butterflies on the 16-element tile; pure scalar FFMA form:
// slot0 <- (x0 + w*y1, y0 - w*x1), slot1 <- (x1 + w*y0, y1 - w*x0)
#define APPLY_GROUP(amp, g)                                                  \
    do {                                                                     \
        _Pragma("unroll")                                                    \
        for (int j = 0; j < 4; ++j) {                                        \
            int gi = cfg.gidx[g][j];                                         \
            float w = (gi < 0) ? 0.0f : wv[gi];                              \
            _Pragma("unroll")                                                \
            for (int t = 0; t < 16; ++t) {                                   \
                if (t & (1 << j)) continue;                                  \
                int tb = t | (1 << j);                                       \
                float x0 = amp[t].x,  y0 = amp[t].y;                         \
                float x1 = amp[tb].x, y1 = amp[tb].y;                        \
                amp[t].x  = fmaf(w, y1, x0);                                 \
                amp[t].y  = fmaf(-w, x1, y0);                                \
                amp[tb].x = fmaf(w, y0, x1);                                 \
                amp[tb].y = fmaf(-w, x0, y1);                                \
            }                                                                \
        }                                                                    \
    } while (0)

__global__ void __launch_bounds__(NTHREADS, 1)
qsim_kernel(const float* __restrict__ x, const float* __restrict__ params,
            float* __restrict__ out, Cfg cfg)
{
    extern __shared__ float2 st[];            // 16384 amplitudes = 128 KB
    __shared__ float xc[NQ], xs[NQ];
    __shared__ float wv[NGATES], den[NGATES];
    __shared__ unsigned char ufl[NGATES];
    __shared__ float TL[128], TH[128];        // magnitude product tables (logical bits)
    __shared__ unsigned short silo[128], sihi[128];  // sigma^-1 tables
    __shared__ unsigned short T0[32], T1[32]; // base sign words
    __shared__ float red[NWARPS][NQ];
    __shared__ float scr[NTHREADS * 17];
    __shared__ float s_scale2;
    __shared__ unsigned s_flip;

    const int b   = blockIdx.x;
    const int tid = threadIdx.x;
    const int ng  = cfg.ngroups;

    // ---- phase 1: trig + sigma^-1 table copy ----
    if (tid < NQ) {
        float v = 0.5f * x[b * NQ + tid];
        xc[tid] = cosf(v);
        xs[tid] = sinf(v);
    }
    {
        int g = tid - 32;
        if (g >= 0 && g < NGATES) {
            float v = 0.5f * params[g];
            float c = cosf(v), s = sinf(v);
            bool tf = fabsf(c) >= fabsf(s);
            wv[g]  = tf ? (s / c) : (-c / s);
            den[g] = tf ? c : s;
            ufl[g] = tf ? 0 : 1;
        }
    }
    if (tid >= 96 && tid < 224)  silo[tid - 96]  = cfg.illo[tid - 96];
    if (tid >= 224 && tid < 352) sihi[tid - 224] = cfg.ilhi[tid - 224];
    __syncthreads();

    // ---- phase 2: product tables, sign tables, global scale/D ----
    if (tid < 128) {
        float m = 1.0f;
        #pragma unroll
        for (int k = 0; k < 7; ++k) m *= ((tid >> k) & 1) ? xs[13 - k] : xc[13 - k];
        TL[tid] = m;
    } else if (tid < 256) {
        int h = tid - 128;
        float m = 1.0f;
        #pragma unroll
        for (int k = 0; k < 7; ++k) m *= ((h >> k) & 1) ? xs[6 - k] : xc[6 - k];
        TH[h] = m;
    } else if (tid < 320) {
        int a = tid - 256;
        unsigned i10 = (a < 32) ? (unsigned)a : ((unsigned)(a - 32) << 5);
        unsigned p = expand4(i10, cfg.lm[ng - 1]);
        unsigned w = 0;
        #pragma unroll
        for (int q = 0; q < NQ; ++q)
            w |= (unsigned)(__popc(p & (unsigned)cfg.meas[q]) & 1) << q;
        if (a < 32) T0[a] = (unsigned short)w; else T1[a - 32] = (unsigned short)w;
    } else if (tid == 320) {
        unsigned D = 0;
        float sc = 1.0f;
        for (int g = 0; g < NGATES; ++g) {
            sc *= den[g];
            if (ufl[g]) D ^= (unsigned)cfg.gseq[g];
        }
        unsigned fl = 0;
        for (int q = 0; q < NQ; ++q)
            fl |= (unsigned)(__popc(D & (unsigned)cfg.meas[q]) & 1) << q;
        s_flip = fl;
        s_scale2 = sc * sc;
    }
    __syncthreads();

    // ---- group 0: fused init ----
    #pragma unroll 1
    for (int r = 0; r < 2; ++r) {
        const unsigned i = tid + (r << 9);
        unsigned p = expand4(i, cfg.lm[0]);
        unsigned B = (unsigned)silo[p & 127] ^ (unsigned)sihi[p >> 7];
        float2 amp[16];
        #pragma unroll
        for (int t = 0; t < 16; ++t) {
            unsigned Bt = B ^ (unsigned)cfg.c0log[t];
            float mag = TH[Bt >> 7] * TL[Bt & 127];
            int m = __popc(Bt) & 3;
            amp[t].x = (m == 0) ? mag : ((m == 2) ? -mag : 0.0f);
            amp[t].y = (m == 1) ? -mag : ((m == 3) ? mag : 0.0f);
        }
        APPLY_GROUP(amp, 0);
        #pragma unroll
        for (int t = 0; t < 16; ++t)
            st[p ^ (unsigned)cfg.combo[0][t]] = amp[t];
    }
    __syncthreads();

    // ---- middle groups ----
    #pragma unroll 1
    for (int g = 1; g < ng - 1; ++g) {
        #pragma unroll 1
        for (int r = 0; r < 2; ++r) {
            const unsigned i = tid + (r << 9);
            unsigned p = expand4(i, cfg.lm[g]);
            float2 amp[16];
            #pragma unroll
            for (int t = 0; t < 16; ++t)
                amp[t] = st[p ^ (unsigned)cfg.combo[g][t]];
            APPLY_GROUP(amp, g);
            #pragma unroll
            for (int t = 0; t < 16; ++t)
                st[p ^ (unsigned)cfg.combo[g][t]] = amp[t];
        }
        __syncthreads();
    }

    // ---- last group + fused measurement ----
    float acc[NQ];
    #pragma unroll
    for (int q = 0; q < NQ; ++q) acc[q] = 0.0f;
    {
        const int g = ng - 1;
        const unsigned flip = s_flip;
        #pragma unroll 1
        for (int r = 0; r < 2; ++r) {
            const unsigned i = tid + (r << 9);
            unsigned p = expand4(i, cfg.lm[g]);
            float2 amp[16];
            #pragma unroll
            for (int t = 0; t < 16; ++t)
                amp[t] = st[p ^ (unsigned)cfg.combo[g][t]];
            APPLY_GROUP(amp, g);

            float pr[16];
            #pragma unroll
            for (int t = 0; t < 16; ++t)
                pr[t] = amp[t].x * amp[t].x + amp[t].y * amp[t].y;
            #pragma unroll
            for (int j = 0; j < 4; ++j) {
                #pragma unroll
                for (int t = 0; t < 16; ++t) {
                    if (t & (1 << j)) continue;
                    int tb = t | (1 << j);
                    float a = pr[t], bb = pr[tb];
                    pr[t] = a + bb; pr[tb] = a - bb;
                }
            }
            #pragma unroll
            for (int t = 0; t < 16; ++t) scr[tid * 17 + t] = pr[t];
            unsigned wb = (unsigned)T0[i & 31] ^ (unsigned)T1[(i >> 5) & 31] ^ flip;
            #pragma unroll
            for (int q = 0; q < NQ; ++q) {
                float v = scr[tid * 17 + cfg.vq[q]];
                acc[q] += ((wb >> q) & 1) ? -v : v;
            }
        }
    }

    // ---- reduce + scale ----
    #pragma unroll
    for (int q = 0; q < NQ; ++q) {
        #pragma unroll
        for (int o = 16; o > 0; o >>= 1)
            acc[q] += __shfl_down_sync(0xffffffffu, acc[q], o);
    }
    const int warp = tid >> 5, lane = tid & 31;
    if (lane == 0) {
        #pragma unroll
        for (int q = 0; q < NQ; ++q) red[warp][q] = acc[q];
    }
    __syncthreads();
    if (tid < NQ) {
        float t = 0.0f;
        #pragma unroll
        for (int w = 0; w < NWARPS; ++w) t += red[w][tid];
        out[b * NQ + tid] = t * s_scale2;
    }
}

// ================= host side =================
static unsigned P_gate(unsigned v, int q) {
    int c = NQ - 1 - q;
    int t = NQ - 1 - ((q + 1) % NQ);
    return v ^ (((v >> c) & 1u) << t);
}
static unsigned Capply(unsigned v)    { for (int q = 0;      q < NQ; ++q) v = P_gate(v, q); return v; }
static unsigned Cinvapply(unsigned v) { for (int q = NQ - 1; q >= 0; --q) v = P_gate(v, q); return v; }

static unsigned mapv(const unsigned* cols, unsigned x) {
    unsigned r = 0;
    while (x) { int j = __builtin_ctz(x); r ^= cols[j]; x &= x - 1; }
    return r;
}

static int invert14(const unsigned* sc, unsigned* si) {
    unsigned rowA[NQ], rowB[NQ];
    for (int i = 0; i < NQ; ++i) {
        unsigned a = 0;
        for (int j = 0; j < NQ; ++j) a |= ((sc[j] >> i) & 1u) << j;
        rowA[i] = a; rowB[i] = 1u << i;
    }
    for (int c = 0; c < NQ; ++c) {
        int p = -1;
        for (int r = c; r < NQ; ++r) if ((rowA[r] >> c) & 1u) { p = r; break; }
        if (p < 0) return 0;
        unsigned ta = rowA[p], tb = rowB[p];
        rowA[p] = rowA[c]; rowB[p] = rowB[c]; rowA[c] = ta; rowB[c] = tb;
        for (int r = 0; r < NQ; ++r)
            if (r != c && ((rowA[r] >> c) & 1u)) { rowA[r] ^= rowA[c]; rowB[r] ^= rowB[c]; }
    }
    for (int j = 0; j < NQ; ++j) {
        unsigned v = 0;
        for (int i = 0; i < NQ; ++i) v |= ((rowB[i] >> j) & 1u) << i;
        si[j] = v;
    }
    return 1;
}

struct GRP { unsigned mask[4]; signed char gid[4]; unsigned char piv[4]; };

static bool spanok(const unsigned* m, int n, unsigned hm) {
    for (int c = 1; c < (1 << n); ++c) {
        unsigned v = 0;
        for (int j = 0; j < n; ++j) if ((c >> j) & 1) v ^= m[j];
        if ((v & hm) == 0) return false;   // dependent (v==0) or low-only span element
    }
    return true;
}

static int pack_groups(const unsigned* seqv, GRP* grp, bool relax) {
    const unsigned hm = relax ? 0x3FFFu : HIMASK;
    const int lowb = relax ? 0 : 5;
    int ng = 0, cnt = 0;
    unsigned cur[4]; signed char cgid[4];

    auto closeg = [&]() -> bool {
        while (cnt < 4) {
            bool ok = false;
            for (int b = 13; b >= lowb && !ok; --b) {
                cur[cnt] = 1u << b;
                if (spanok(cur, cnt + 1, hm)) { cgid[cnt] = -1; ++cnt; ok = true; }
            }
            if (!ok) return false;
        }
        unsigned pos[NQ]; memset(pos, 0, sizeof(pos));
        unsigned char pv[4]; int np = 0;
        for (int j = 0; j < 4; ++j) {
            unsigned v = cur[j];
            for (int b = 13; b >= lowb; --b) {
                if (!((v >> b) & 1u)) continue;
                if (pos[b]) { v ^= pos[b]; continue; }
                pos[b] = v; pv[np++] = (unsigned char)b; break;
            }
        }
        if (np != 4 || ng >= MAXG) return false;
        for (int a = 0; a < 4; ++a)
            for (int b2 = a + 1; b2 < 4; ++b2)
                if (pv[b2] < pv[a]) { unsigned char t = pv[a]; pv[a] = pv[b2]; pv[b2] = t; }
        for (int j = 0; j < 4; ++j) {
            grp[ng].mask[j] = cur[j]; grp[ng].gid[j] = cgid[j]; grp[ng].piv[j] = pv[j];
        }
        ++ng; cnt = 0;
        return true;
    };

    for (int s = 0; s < NGATES; ++s) {
        bool placed = false;
        if (cnt < 4) {
            cur[cnt] = seqv[s];
            if (spanok(cur, cnt + 1, hm)) { cgid[cnt] = (signed char)s; ++cnt; placed = true; }
        }
        if (!placed) {
            if (!closeg()) return -1;
            cur[0] = seqv[s];
            if (!spanok(cur, 1, hm)) return -1;
            cgid[0] = (signed char)s; cnt = 1;
        }
    }
    if (cnt > 0 && !closeg()) return -1;
    return ng;
}

extern "C" void kernel_launch(void* const* d_in, const int* in_sizes, int n_in,
                              void* d_out, int out_size)
{
    unsigned rngs = 0x12345u;
    auto rnd = [&]() { rngs = rngs * 1664525u + 1013904223u; return rngs >> 8; };

    // base-frame gate masks and measurement masks (validated in R1/R2)
    unsigned seq[NGATES];
    int si_ = 0;
    for (int l = 0; l < NL; ++l)
        for (int q = 0; q < NQ; ++q) {
            unsigned m = 1u << (NQ - 1 - q);
            for (int k = 0; k < l; ++k) m = Cinvapply(m);
            seq[si_++] = m;
        }
    unsigned col[NQ], mo[NQ];
    for (int j = 0; j < NQ; ++j) {
        unsigned v = 1u << j;
        for (int k = 0; k < NL; ++k) v = Capply(v);
        col[j] = v;
    }
    for (int q = 0; q < NQ; ++q) {
        unsigned mask = 0;
        int t = NQ - 1 - q;
        for (int j = 0; j < NQ; ++j) mask |= ((col[j] >> t) & 1u) << j;
        mo[q] = mask;
    }

    // sigma search: all groups clear of bits 0..4; init-table projection near-full rank
    unsigned sc[NQ], siv[NQ], seqv[NGATES];
    GRP grp[MAXG];
    int ng = -1;
    bool found = false;
    for (int trial = 0; trial < 4096 && !found; ++trial) {
        for (int j = 0; j < NQ; ++j) sc[j] = rnd() & 0x3FFFu;
        if (!invert14(sc, siv)) continue;
        for (int s = 0; s < NGATES; ++s) seqv[s] = mapv(sc, seq[s]);
        int n2 = pack_groups(seqv, grp, false);
        if (n2 < 0 || n2 > 16) continue;
        {   // rank of {siv[0..4] & 31} >= 4 (keeps init table lookups near conflict-free)
            unsigned pos[5] = {0, 0, 0, 0, 0}; int rk = 0;
            for (int j = 0; j < 5; ++j) {
                unsigned v = siv[j] & 31u;
                for (int b = 4; b >= 0; --b) {
                    if (!((v >> b) & 1u)) continue;
                    if (pos[b]) { v ^= pos[b]; continue; }
                    pos[b] = v; ++rk; break;
                }
            }
            if (rk < 4) continue;
        }
        ng = n2; found = true;
    }
    if (!found) {  // fallback: identity sigma, unconstrained grouping (R2 behavior)
        for (int j = 0; j < NQ; ++j) { sc[j] = 1u << j; siv[j] = 1u << j; }
        for (int s = 0; s < NGATES; ++s) seqv[s] = seq[s];
        ng = pack_groups(seqv, grp, true);
    }

    Cfg cfg;
    memset(&cfg, 0, sizeof(cfg));
    cfg.ngroups = ng;
    for (int g = 0; g < ng; ++g) {
        for (int t = 0; t < 16; ++t) {
            unsigned c = 0;
            for (int j = 0; j < 4; ++j) if ((t >> j) & 1) c ^= grp[g].mask[j];
            cfg.combo[g][t] = (unsigned short)c;
        }
        for (int j = 0; j < 4; ++j) {
            cfg.lm[g][j]   = (unsigned short)((1u << grp[g].piv[j]) - 1u);
            cfg.gidx[g][j] = grp[g].gid[j];
        }
    }
    for (int s = 0; s < NGATES; ++s) cfg.gseq[s] = (unsigned short)seqv[s];
    for (int q = 0; q < NQ; ++q) {          // meas' = sigma^-T (mo)
        unsigned m2 = 0;
        for (int j = 0; j < NQ; ++j)
            m2 |= (unsigned)(__builtin_popcount(siv[j] & mo[q]) & 1) << j;
        cfg.meas[q] = (unsigned short)m2;
    }
    for (int v = 0; v < 128; ++v) cfg.illo[v] = (unsigned short)mapv(siv, (unsigned)v);
    for (int h = 0; h < 128; ++h) cfg.ilhi[h] = (unsigned short)mapv(siv, ((unsigned)h) << 7);
    for (int t = 0; t < 16; ++t)  cfg.c0log[t] = (unsigned short)mapv(siv, cfg.combo[0][t]);
    for (int q = 0; q < NQ; ++q) {
        unsigned v = 0;
        for (int j = 0; j < 4; ++j)
            v |= (unsigned)(__builtin_popcount(grp[ng - 1].mask[j] & cfg.meas[q]) & 1) << j;
        cfg.vq[q] = (unsigned char)v;
    }

    const int batch = in_sizes[0] / NQ;
    cudaFuncSetAttribute(qsim_kernel, cudaFuncAttributeMaxDynamicSharedMemorySize,
                         DIM * (int)sizeof(float2));
    qsim_kernel<<<batch, NTHREADS, DIM * sizeof(float2)>>>(
        (const float*)d_in[0], (const float*)d_in[1], (float*)d_out, cfg);
}

// round 7
// speedup vs baseline: 10.4367x; 2.9580x over previous
#include <cuda_runtime.h>
#include <string.h>
#include <math.h>

#define NQ 14
#define NL 4
#define DIM 16384
#define NTH 512
#define NWARPS 16
#define KA 32                 // amps per thread
#define NGATES 56

// Param-only diagonal phase table e^{i*phi_theta(p)}; built by setup kernel.
__device__ float2 g_E[DIM];

struct SCfg { unsigned short mu[NGATES]; };   // sign masks per gate (storage frame)
struct MCfg { unsigned short colM[NQ]; };     // columns of sigma = C'^{-4}

__global__ void __launch_bounds__(512)
qsetup(const float* __restrict__ params, SCfg c)
{
    const int p = blockIdx.x * 512 + threadIdx.x;
    float ph = 0.f;
    #pragma unroll
    for (int g = 0; g < NGATES; ++g) {
        float h = 0.5f * params[g];
        ph += (__popc(p & (int)c.mu[g]) & 1) ? h : -h;   // exponent (theta/2)(2b-1)
    }
    float s, co;
    sincosf(ph, &s, &co);
    g_E[p] = make_float2(co, s);
}

__global__ void __launch_bounds__(NTH, 1)
qmain(const float* __restrict__ x, float* __restrict__ out, MCfg c)
{
    extern __shared__ float2 st[];            // full state, 128 KB
    __shared__ unsigned short Slo[128], Shi[128];   // sigma linear-map tables
    __shared__ float2 Cxl[128], Cxh[128];     // x-phase complex tables over logical bits
    __shared__ float xh[NQ];
    __shared__ float red[NWARPS][NQ];

    const int b = blockIdx.x, tid = threadIdx.x;

    if (tid < NQ) xh[tid] = 0.5f * x[b * NQ + tid];
    __syncthreads();

    if (tid < 128) {
        unsigned lo = 0, hi = 0;
        #pragma unroll
        for (int j = 0; j < 7; ++j)
            if ((tid >> j) & 1) { lo ^= c.colM[j]; hi ^= c.colM[j + 7]; }
        Slo[tid] = (unsigned short)lo;
        Shi[tid] = (unsigned short)hi;
        // logical bits 0..6 <-> qubits 13..7
        float a = 0.f;
        #pragma unroll
        for (int m = 0; m < 7; ++m) a += ((tid >> m) & 1) ? xh[13 - m] : -xh[13 - m];
        float s, co; sincosf(a, &s, &co);
        Cxl[tid] = make_float2(co, s);
    } else if (tid < 256) {
        const int i = tid - 128;
        // logical bits 7..13 <-> qubits 6..0
        float a = 0.f;
        #pragma unroll
        for (int m = 0; m < 7; ++m) a += ((i >> m) & 1) ? xh[6 - m] : -xh[6 - m];
        float s, co; sincosf(a, &s, &co);
        Cxh[i] = make_float2(co, s);
    }
    __syncthreads();

    // ---- pass 1: a_p = E_theta[p] * Bx(L(p)),  L = sigma(p) ----
    float2 amp[KA];
    #pragma unroll
    for (int k = 0; k < KA; ++k) {
        const int p = tid + (k << 9);
        float2 E = g_E[p];
        unsigned L = (unsigned)Slo[p & 127] ^ (unsigned)Shi[p >> 7];
        float2 cl = Cxl[L & 127];
        float2 ch = Cxh[L >> 7];
        float br = cl.x * ch.x - cl.y * ch.y;
        float bi = cl.x * ch.y + cl.y * ch.x;
        float ar = E.x * br - E.y * bi;
        float ai = E.x * bi + E.y * br;
        amp[k] = make_float2(ar, ai);
        st[p] = amp[k];
    }
    __syncthreads();

    // ---- pass 2: <X_m> = sum_p Re(conj(a_p) a_{p ^ (1<<m)}) ----
    float acc[NQ];
    #pragma unroll
    for (int m = 0; m < NQ; ++m) acc[m] = 0.f;

    // bits 0..4: lane bits -> shfl.bfly
    #pragma unroll
    for (int j = 0; j < 5; ++j) {
        #pragma unroll
        for (int k = 0; k < KA; ++k) {
            float sx = __shfl_xor_sync(0xffffffffu, amp[k].x, 1 << j);
            float sy = __shfl_xor_sync(0xffffffffu, amp[k].y, 1 << j);
            acc[j] += amp[k].x * sx + amp[k].y * sy;
        }
    }
    // bits 5..8: warp bits -> smem gather (conflict-free: lane bits intact)
    #pragma unroll
    for (int j = 0; j < 4; ++j) {
        #pragma unroll
        for (int k = 0; k < KA; ++k) {
            const int p = (tid + (k << 9)) ^ (32 << j);
            float2 q2 = st[p];
            acc[5 + j] += amp[k].x * q2.x + amp[k].y * q2.y;
        }
    }
    // bits 9..13: per-thread k bits -> in-register
    #pragma unroll
    for (int j = 0; j < 5; ++j) {
        #pragma unroll
        for (int k = 0; k < KA; ++k) {
            const int kb = k ^ (1 << j);
            acc[9 + j] += amp[k].x * amp[kb].x + amp[k].y * amp[kb].y;
        }
    }

    // ---- reduce across threads ----
    #pragma unroll
    for (int m = 0; m < NQ; ++m) {
        #pragma unroll
        for (int o = 16; o > 0; o >>= 1)
            acc[m] += __shfl_down_sync(0xffffffffu, acc[m], o);
    }
    const int warp = tid >> 5, lane = tid & 31;
    if (lane == 0) {
        #pragma unroll
        for (int m = 0; m < NQ; ++m) red[warp][m] = acc[m];
    }
    __syncthreads();
    if (tid < NQ) {
        // output qubit q <-> storage bit m = 13 - q; amps unit-modulus -> scale 2^-14
        float t = 0.f;
        #pragma unroll
        for (int w = 0; w < NWARPS; ++w) t += red[w][13 - tid];
        out[b * NQ + tid] = t * (1.0f / 16384.0f);
    }
}

// ================= host side =================
// Conjugated (reversed) CNOT ring: original CNOT(q, q+1) -> CNOT(ctrl=q+1, tgt=q).
// Index map on basis states (qubit 0 = MSB = bit 13).
static unsigned Pp(unsigned v, int q) {
    int cc = 13 - ((q + 1) % NQ);
    int tt = 13 - q;
    return v ^ (((v >> cc) & 1u) << tt);
}
static unsigned C1(unsigned v)  { for (int q = 0;  q < NQ;  ++q) v = Pp(v, q); return v; }
static unsigned C1i(unsigned v) { for (int q = NQ - 1; q >= 0; --q) v = Pp(v, q); return v; }

extern "C" void kernel_launch(void* const* d_in, const int* in_sizes, int n_in,
                              void* d_out, int out_size)
{
    // sigma = C'^{-4}: columns
    unsigned colM[NQ];
    for (int j = 0; j < NQ; ++j) {
        unsigned v = 1u << j;
        for (int r = 0; r < NL; ++r) v = C1i(v);
        colM[j] = v;
    }

    SCfg sc; MCfg mc;
    memset(&sc, 0, sizeof(sc));
    memset(&mc, 0, sizeof(mc));
    for (int j = 0; j < NQ; ++j) mc.colM[j] = (unsigned short)colM[j];

    // Gate sign masks: layer l acts with logical map A_l = C'^{l} o sigma = C'^{l-4}.
    // RZ on qubit q reads bit m = 13-q of A_l(p): mask = row_m(A_l).
    for (int l = 0; l < NL; ++l) {
        unsigned cn[NQ];
        for (int j = 0; j < NQ; ++j) {
            unsigned v = colM[j];
            for (int r = 0; r < l; ++r) v = C1(v);
            cn[j] = v;
        }
        for (int q = 0; q < NQ; ++q) {
            int m = 13 - q;
            unsigned mask = 0;
            for (int j = 0; j < NQ; ++j) mask |= ((cn[j] >> m) & 1u) << j;
            sc.mu[l * NQ + q] = (unsigned short)mask;
        }
    }

    const float* x = (const float*)d_in[0];
    const float* params = (const float*)d_in[1];
    const int batch = in_sizes[0] / NQ;

    qsetup<<<DIM / 512, 512>>>(params, sc);

    cudaFuncSetAttribute(qmain, cudaFuncAttributeMaxDynamicSharedMemorySize,
                         DIM * (int)sizeof(float2));
    qmain<<<batch, NTH, DIM * sizeof(float2)>>>(x, (float*)d_out, mc);
}